// round 10
// baseline (speedup 1.0000x reference)
#include <cuda_runtime.h>
#include <math.h>
#include <cstdint>

// Problem constants
#define B_  4
#define N_  2048
#define E_  512
#define H_  8
#define D_  64
#define BH_ 32   // B_*H_

// ---------------- scratch (static __device__; no allocations allowed) -------
// "p" = within-8-column pair-interleaved layout: pos 2j <- col j, 2j+1 <- col j+4
__device__ float g_xrp [B_ * N_ * E_];    // x, e-cols permuted, tf32-rounded
__device__ float g_Wkp [E_ * E_];         // Wk, e-cols permuted, rounded
__device__ float g_Wvp [E_ * E_];         // Wv, e-cols permuted, rounded
__device__ float g_Kp  [BH_ * N_ * D_];   // K [bh][n][d-permuted], rounded
__device__ float g_VTp [BH_ * D_ * N_];   // V^T [bh][d][key-permuted], rounded
__device__ float g_norm2[BH_ * N_];
__device__ float g_gmax2[BH_];

// ---------------- helpers (sm_80-era PTX only) --------------------------------
__device__ __forceinline__ void mma_tf32(float* d, const uint32_t* a,
                                         uint32_t b0, uint32_t b1) {
    asm volatile(
        "mma.sync.aligned.m16n8k8.row.col.f32.tf32.tf32.f32 "
        "{%0,%1,%2,%3}, {%4,%5,%6,%7}, {%8,%9}, {%0,%1,%2,%3};\n"
        : "+f"(d[0]), "+f"(d[1]), "+f"(d[2]), "+f"(d[3])
        : "r"(a[0]), "r"(a[1]), "r"(a[2]), "r"(a[3]), "r"(b0), "r"(b1));
}
__device__ __forceinline__ uint32_t f2tf(float x) {
    uint32_t r; asm("cvt.rna.tf32.f32 %0, %1;" : "=r"(r) : "f"(x)); return r;
}
__device__ __forceinline__ float rtf(float x) { return __uint_as_float(f2tf(x)); }
__device__ __forceinline__ uint32_t smem_u32(const void* p) {
    uint32_t a;
    asm("{ .reg .u64 t; cvta.to.shared.u64 t, %1; cvt.u32.u64 %0, t; }"
        : "=r"(a) : "l"(p));
    return a;
}
#define CP16(dst, src) \
    asm volatile("cp.async.cg.shared.global [%0], [%1], 16;" :: "r"(dst), "l"(src) : "memory")
#define CP_COMMIT() asm volatile("cp.async.commit_group;" ::: "memory")
#define CP_WAIT(n)  asm volatile("cp.async.wait_group %0;" :: "n"(n) : "memory")

// C-frag (two rows x 2 cols) -> A-frag relayout via intra-quad shuffles
__device__ __forceinline__ void relayout(uint32_t c0v, uint32_t c1v,
                                         uint32_t c2v, uint32_t c3v,
                                         int src1, int src2, int qodd,
                                         uint32_t* a) {
    uint32_t t0, t1;
    t0 = __shfl_sync(0xffffffffu, c0v, src1);
    t1 = __shfl_sync(0xffffffffu, c1v, src1);
    a[0] = qodd ? t1 : t0;
    t0 = __shfl_sync(0xffffffffu, c2v, src1);
    t1 = __shfl_sync(0xffffffffu, c3v, src1);
    a[1] = qodd ? t1 : t0;
    t0 = __shfl_sync(0xffffffffu, c0v, src2);
    t1 = __shfl_sync(0xffffffffu, c1v, src2);
    a[2] = qodd ? t1 : t0;
    t0 = __shfl_sync(0xffffffffu, c2v, src2);
    t1 = __shfl_sync(0xffffffffu, c3v, src2);
    a[3] = qodd ? t1 : t0;
}

// ---------------- pre-round + pair-permute (within-8 e-columns) --------------
// out[8g + 2j] = in[8g + j], out[8g + 2j + 1] = in[8g + j + 4]
__global__ void round_perm(const float* __restrict__ src,
                           float* __restrict__ dst, int n4) {
    int i = blockIdx.x * 256 + threadIdx.x;
    if (i >= n4) return;
    int base = 8 * (i >> 1) + 2 * (i & 1);
    float2 a = *(const float2*)(src + base);
    float2 b = *(const float2*)(src + base + 4);
    float4 o = make_float4(rtf(a.x), rtf(b.x), rtf(a.y), rtf(b.y));
    *(float4*)(dst + 4 * i) = o;
}

// ---------------- fused K+V projection GEMM (tf32 mma, cp.async 2-stage) -----
// Tile 128m x 64c (one head), K AND V in the same CTA (shared x/A-frags).
// All smem fragment loads are paired LDS.64 (layouts pre-permuted in gmem).
#define PJ_STR 44
#define PJ_KOF (128 * PJ_STR)
#define PJ_VOF (192 * PJ_STR)
#define PJ_BUF (256 * PJ_STR)                 // floats per stage: 11264
#define PJ_SMEM (2 * PJ_BUF * 4)              // 90112 B

__device__ __forceinline__ void pj_issue(uint32_t sb, int stage, int k0,
                                         int m0, int c0, int tid) {
    uint32_t base = sb + stage * (PJ_BUF * 4);
#pragma unroll
    for (int it = 0; it < 4; it++) {           // xs: 128x32 = 1024 chunks
        int i = it * 256 + tid;
        int r = i >> 3, c4 = (i & 7) * 4;
        CP16(base + (r * PJ_STR + c4) * 4,
             g_xrp + (size_t)(m0 + r) * E_ + k0 + c4);
    }
#pragma unroll
    for (int it = 0; it < 2; it++) {           // wsK: 512 chunks
        int i = it * 256 + tid;
        int r = i >> 3, c4 = (i & 7) * 4;
        CP16(base + (PJ_KOF + r * PJ_STR + c4) * 4,
             g_Wkp + (size_t)(c0 + r) * E_ + k0 + c4);
    }
#pragma unroll
    for (int it = 0; it < 2; it++) {           // wsV: 512 chunks
        int i = it * 256 + tid;
        int r = i >> 3, c4 = (i & 7) * 4;
        CP16(base + (PJ_VOF + r * PJ_STR + c4) * 4,
             g_Wvp + (size_t)(c0 + r) * E_ + k0 + c4);
    }
    CP_COMMIT();
}

__global__ void __launch_bounds__(256, 2) proj_mma(const float* __restrict__ bk,
                                                   const float* __restrict__ bv) {
    extern __shared__ uint32_t smu[];
    uint32_t sb = smem_u32(smu);
    int tid = threadIdx.x;
    int w = tid >> 5, lane = tid & 31;
    int qq = lane & 3, g = lane >> 2;
    int m0 = blockIdx.x * 128;
    int h  = blockIdx.y;
    int c0 = h * 64;

    float accK[8][4], accV[8][4];
#pragma unroll
    for (int i = 0; i < 8; i++)
#pragma unroll
        for (int j = 0; j < 4; j++) { accK[i][j] = 0.f; accV[i][j] = 0.f; }

    pj_issue(sb, 0, 0, m0, c0, tid);

    for (int ec = 0; ec < 16; ec++) {
        if (ec < 15) pj_issue(sb, (ec + 1) & 1, (ec + 1) * 32, m0, c0, tid);
        if (ec < 15) { CP_WAIT(1); } else { CP_WAIT(0); }
        __syncthreads();

        const uint32_t* bf = smu + (ec & 1) * PJ_BUF;
        uint32_t af[4][4];
#pragma unroll
        for (int kk = 0; kk < 4; kk++) {
            uint2 lo = *(const uint2*)&bf[(16 * w + g) * PJ_STR + 8 * kk + 2 * qq];
            uint2 hi = *(const uint2*)&bf[(16 * w + g + 8) * PJ_STR + 8 * kk + 2 * qq];
            af[kk][0] = lo.x; af[kk][1] = hi.x; af[kk][2] = lo.y; af[kk][3] = hi.y;
        }
#pragma unroll
        for (int nt = 0; nt < 8; nt++) {
#pragma unroll
            for (int kk = 0; kk < 4; kk++) {
                uint2 bK = *(const uint2*)&bf[PJ_KOF + (8 * nt + g) * PJ_STR + 8 * kk + 2 * qq];
                mma_tf32(accK[nt], af[kk], bK.x, bK.y);
                uint2 bV = *(const uint2*)&bf[PJ_VOF + (8 * nt + g) * PJ_STR + 8 * kk + 2 * qq];
                mma_tf32(accV[nt], af[kk], bV.x, bV.y);
            }
        }
        __syncthreads();
    }

    // epilogue
    int r0 = m0 + 16 * w + g;
    int b0i = r0 >> 11, n0i = r0 & 2047;
    int bh = b0i * 8 + h;

    // K -> g_Kp [bh][n][d-permuted]; orig cols (8nt+2qq, +1) land at (p1, p1+2)
    float* Kp0 = g_Kp + ((size_t)bh * N_ + n0i) * D_;
    // V -> g_VTp [bh][d][key-permuted]; key n0i (local g) -> colp, n0i+8 -> colp+8
    int colp = (n0i - g) + (g < 4 ? 2 * g : 2 * g - 7);
#pragma unroll
    for (int nt = 0; nt < 8; nt++) {
        int c = 8 * nt + 2 * qq;                 // orig output col (local)
        float bb0 = bk[c0 + c], bb1 = bk[c0 + c + 1];
        float vb0 = bv[c0 + c], vb1 = bv[c0 + c + 1];
        int p1 = 8 * nt + (qq < 2 ? 4 * qq : 4 * qq - 7);
        Kp0[p1]              = rtf(accK[nt][0] + bb0);
        Kp0[p1 + 2]          = rtf(accK[nt][1] + bb1);
        Kp0[8 * D_ + p1]     = rtf(accK[nt][2] + bb0);
        Kp0[8 * D_ + p1 + 2] = rtf(accK[nt][3] + bb1);

        float* Vp0 = g_VTp + ((size_t)bh * D_ + c) * N_;
        float* Vp1 = g_VTp + ((size_t)bh * D_ + c + 1) * N_;
        Vp0[colp]     = rtf(accV[nt][0] + vb0);
        Vp1[colp]     = rtf(accV[nt][1] + vb1);
        Vp0[colp + 8] = rtf(accV[nt][2] + vb0);
        Vp1[colp + 8] = rtf(accV[nt][3] + vb1);
    }
}

// ---------------- row-norm kernel (perm-invariant row sums) ------------------
__global__ void __launch_bounds__(256) norm_kernel() {
    __shared__ float red[256];
    int bh = blockIdx.x, tid = threadIdx.x;
    const float* Kb = g_Kp + (size_t)bh * N_ * D_;
    float gm = 0.f;
    for (int r = tid; r < N_; r += 256) {
        const float4* p = (const float4*)(Kb + (size_t)r * D_);
        float s = 0.f;
#pragma unroll
        for (int j = 0; j < 16; j++) {
            float4 v = p[j];
            s += v.x * v.x + v.y * v.y + v.z * v.z + v.w * v.w;
        }
        g_norm2[bh * N_ + r] = s;
        gm = fmaxf(gm, s);
    }
    red[tid] = gm;
    __syncthreads();
    for (int o = 128; o; o >>= 1) {
        if (tid < o) red[tid] = fmaxf(red[tid], red[tid + o]);
        __syncthreads();
    }
    if (tid == 0) g_gmax2[bh] = red[0];
}

// ---------------- tf32 mma flash attention -----------------------------------
// 3-buffer cp.async ring (prefetch distance 1) -> ONE barrier per iter.
// All B-fragments are paired LDS.64 (K d-perm, V^T key-perm). 2-way nt ILP.
#define KS_STR 76
#define VP_STR 68
#define AT_VOF (64 * KS_STR)                  // 4864 floats
#define AT_BUF (64 * KS_STR + 64 * VP_STR)    // 9216 floats per stage
#define ATTN_SMEM (3 * AT_BUF * 4)            // 110592 B

__device__ __forceinline__ void at_issue(uint32_t sb, int stage, int k0,
                                         const float* __restrict__ Kpb,
                                         const float* __restrict__ Vpb, int tid) {
    uint32_t base = sb + stage * (AT_BUF * 4);
#pragma unroll
    for (int it = 0; it < 4; it++) {          // K tile: 64 keys x 64 d
        int i = it * 256 + tid;
        int r = i >> 4, c4 = (i & 15) * 4;
        CP16(base + (r * KS_STR + c4) * 4,
             Kpb + (size_t)(k0 + r) * D_ + c4);
    }
#pragma unroll
    for (int it = 0; it < 4; it++) {          // V^T tile: 64 d x 64 keys
        int i = it * 256 + tid;
        int r = i >> 4, c4 = (i & 15) * 4;
        CP16(base + (AT_VOF + r * VP_STR + c4) * 4,
             Vpb + (size_t)r * N_ + k0 + c4);
    }
    CP_COMMIT();
}

__global__ void __launch_bounds__(256, 2) attn_mma(float* __restrict__ out) {
    extern __shared__ uint32_t smu[];
    uint32_t sb = smem_u32(smu);

    int tid = threadIdx.x;
    int w = tid >> 5, lane = tid & 31;
    int qq = lane & 3, g = lane >> 2;
    int quad = lane & 0x1C;
    int src1 = quad | (qq >> 1);
    int src2 = quad | ((qq >> 1) + 2);
    int qodd = qq & 1;
    int q0 = blockIdx.x * 128;
    int bh = blockIdx.y;
    int b = bh >> 3, h = bh & 7;

    const float* Kpb = g_Kp  + (size_t)bh * N_ * D_;
    const float* Vpb = g_VTp + (size_t)bh * D_ * N_;

    // Q fragments: paired float2 gmem loads from d-permuted K
    int qrow = q0 + 16 * w + g;
    uint32_t qf[8][4];
#pragma unroll
    for (int kk = 0; kk < 8; kk++) {
        float2 lo = *(const float2*)&Kpb[(size_t)qrow * D_ + 8 * kk + 2 * qq];
        float2 hi = *(const float2*)&Kpb[(size_t)(qrow + 8) * D_ + 8 * kk + 2 * qq];
        qf[kk][0] = __float_as_uint(lo.x);
        qf[kk][1] = __float_as_uint(hi.x);
        qf[kk][2] = __float_as_uint(lo.y);
        qf[kk][3] = __float_as_uint(hi.y);
    }

    float gmax = g_gmax2[bh];
    float mhat0 = sqrtf(g_norm2[bh * N_ + qrow] * gmax);
    float mhat8 = sqrtf(g_norm2[bh * N_ + qrow + 8] * gmax);

    float oAcc[8][4];
#pragma unroll
    for (int i = 0; i < 8; i++)
#pragma unroll
        for (int j = 0; j < 4; j++) oAcc[i][j] = 0.f;
    float l0 = 0.f, l8 = 0.f;

    at_issue(sb, 0, 0, Kpb, Vpb, tid);

    int bi = 0, bnext = 1;
    for (int t = 0; t < 32; t++) {
        if (t < 31) at_issue(sb, bnext, (t + 1) * 64, Kpb, Vpb, tid);
        if (t < 31) { CP_WAIT(1); } else { CP_WAIT(0); }
        __syncthreads();

        const uint32_t* Ksb = smu + bi * AT_BUF;
        const uint32_t* Vsb = Ksb + AT_VOF;
        bi = bnext; bnext = (bnext == 2) ? 0 : bnext + 1;

#pragma unroll
        for (int nt2 = 0; nt2 < 8; nt2 += 2) {
            // ---- S for two key-groups (2 independent streams) ----
            float sA[2][4], sB[2][4];
#pragma unroll
            for (int u = 0; u < 2; u++)
#pragma unroll
                for (int j = 0; j < 4; j++) { sA[u][j] = 0.f; sB[u][j] = 0.f; }
#pragma unroll
            for (int kk = 0; kk < 4; kk++) {
#pragma unroll
                for (int u = 0; u < 2; u++) {
                    int row = (8 * (nt2 + u) + g) * KS_STR;
                    uint2 p0 = *(const uint2*)&Ksb[row + 8 * kk + 2 * qq];
                    mma_tf32(sA[u], qf[kk], p0.x, p0.y);
                    uint2 p1 = *(const uint2*)&Ksb[row + 8 * (kk + 4) + 2 * qq];
                    mma_tf32(sB[u], qf[kk + 4], p1.x, p1.y);
                }
            }
            // ---- exp + relayout (both streams) ----
            uint32_t a2[2][4];
#pragma unroll
            for (int u = 0; u < 2; u++) {
                float p0 = __expf(sA[u][0] + sB[u][0] - mhat0);
                float p1 = __expf(sA[u][1] + sB[u][1] - mhat0);
                float p2 = __expf(sA[u][2] + sB[u][2] - mhat8);
                float p3 = __expf(sA[u][3] + sB[u][3] - mhat8);
                l0 += p0 + p1;
                l8 += p2 + p3;
                relayout(f2tf(p0), f2tf(p1), f2tf(p2), f2tf(p3),
                         src1, src2, qodd, a2[u]);
            }
            // ---- O += P V (paired B loads from key-permuted V^T) ----
#pragma unroll
            for (int u = 0; u < 2; u++) {
#pragma unroll
                for (int vt = 0; vt < 8; vt++) {
                    uint2 bv = *(const uint2*)&Vsb[(8 * vt + g) * VP_STR +
                                                   8 * (nt2 + u) + 2 * qq];
                    mma_tf32(oAcc[vt], a2[u], bv.x, bv.y);
                }
            }
        }
    }

    // reduce l across the quad
    l0 += __shfl_xor_sync(0xffffffffu, l0, 1);
    l0 += __shfl_xor_sync(0xffffffffu, l0, 2);
    l8 += __shfl_xor_sync(0xffffffffu, l8, 1);
    l8 += __shfl_xor_sync(0xffffffffu, l8, 2);

    const float inv = 0.04419417382415922f;   // 1/sqrt(512)
    float sc0 = inv / l0, sc8 = inv / l8;

    float* op0 = out + ((size_t)b * N_ + qrow) * E_ + h * 64;
    float* op8 = out + ((size_t)b * N_ + qrow + 8) * E_ + h * 64;
#pragma unroll
    for (int vt = 0; vt < 8; vt++) {
        *(float2*)&op0[8 * vt + 2 * qq] = make_float2(oAcc[vt][0] * sc0, oAcc[vt][1] * sc0);
        *(float2*)&op8[8 * vt + 2 * qq] = make_float2(oAcc[vt][2] * sc8, oAcc[vt][3] * sc8);
    }
}

// ---------------- launch ------------------------------------------------------
extern "C" void kernel_launch(void* const* d_in, const int* in_sizes, int n_in,
                              void* d_out, int out_size) {
    const float* x  = (const float*)d_in[0];
    const float* Wk = (const float*)d_in[1];
    const float* bk = (const float*)d_in[2];
    const float* Wv = (const float*)d_in[3];
    const float* bv = (const float*)d_in[4];
    float* out = (float*)d_out;

    float *xp, *Wkp, *Wvp;
    cudaGetSymbolAddress((void**)&xp,  g_xrp);
    cudaGetSymbolAddress((void**)&Wkp, g_Wkp);
    cudaGetSymbolAddress((void**)&Wvp, g_Wvp);

    cudaFuncSetAttribute(proj_mma, cudaFuncAttributeMaxDynamicSharedMemorySize, PJ_SMEM);
    cudaFuncSetAttribute(attn_mma, cudaFuncAttributeMaxDynamicSharedMemorySize, ATTN_SMEM);

    // pre-round + pair-permute inputs (e-columns; A and B permuted identically)
    round_perm<<<(B_ * N_ * E_ / 4 + 255) / 256, 256>>>(x, xp, B_ * N_ * E_ / 4);
    round_perm<<<(E_ * E_ / 4 + 255) / 256, 256>>>(Wk, Wkp, E_ * E_ / 4);
    round_perm<<<(E_ * E_ / 4 + 255) / 256, 256>>>(Wv, Wvp, E_ * E_ / 4);

    // fused K+V projection (shared x tiles / A-fragments)
    proj_mma<<<dim3(64, 8), 256, PJ_SMEM>>>(bk, bv);

    norm_kernel<<<BH_, 256>>>();

    attn_mma<<<dim3(N_ / 128, BH_), 256, ATTN_SMEM>>>(out);
}

// round 11
// speedup vs baseline: 1.3614x; 1.3614x over previous
#include <cuda_runtime.h>
#include <math.h>
#include <cstdint>

// Problem constants
#define B_  4
#define N_  2048
#define E_  512
#define H_  8
#define D_  64
#define BH_ 32   // B_*H_

// ---------------- scratch (static __device__; no allocations allowed) -------
// "p" = within-8-column pair-interleaved layout: pos 2j <- col j, 2j+1 <- col j+4
__device__ float g_xrp [B_ * N_ * E_];    // x, e-cols permuted, tf32-rounded
__device__ float g_Wkp [E_ * E_];         // Wk, e-cols permuted, rounded
__device__ float g_Wvp [E_ * E_];         // Wv, e-cols permuted, rounded
__device__ float g_Kp  [BH_ * N_ * D_];   // K [bh][n][d-permuted], rounded
__device__ float g_V   [BH_ * N_ * D_];   // V [bh][n][d] natural, rounded
__device__ float g_norm2[BH_ * N_];
__device__ float g_gmax2[BH_];

// ---------------- helpers (sm_80-era PTX only) --------------------------------
__device__ __forceinline__ void mma_tf32(float* d, const uint32_t* a,
                                         uint32_t b0, uint32_t b1) {
    asm volatile(
        "mma.sync.aligned.m16n8k8.row.col.f32.tf32.tf32.f32 "
        "{%0,%1,%2,%3}, {%4,%5,%6,%7}, {%8,%9}, {%0,%1,%2,%3};\n"
        : "+f"(d[0]), "+f"(d[1]), "+f"(d[2]), "+f"(d[3])
        : "r"(a[0]), "r"(a[1]), "r"(a[2]), "r"(a[3]), "r"(b0), "r"(b1));
}
__device__ __forceinline__ uint32_t f2tf(float x) {
    uint32_t r; asm("cvt.rna.tf32.f32 %0, %1;" : "=r"(r) : "f"(x)); return r;
}
__device__ __forceinline__ float rtf(float x) { return __uint_as_float(f2tf(x)); }
__device__ __forceinline__ uint32_t smem_u32(const void* p) {
    uint32_t a;
    asm("{ .reg .u64 t; cvta.to.shared.u64 t, %1; cvt.u32.u64 %0, t; }"
        : "=r"(a) : "l"(p));
    return a;
}
#define CP16(dst, src) \
    asm volatile("cp.async.cg.shared.global [%0], [%1], 16;" :: "r"(dst), "l"(src) : "memory")
#define CP_COMMIT() asm volatile("cp.async.commit_group;" ::: "memory")
#define CP_WAIT(n)  asm volatile("cp.async.wait_group %0;" :: "n"(n) : "memory")

// ---------------- pre-round + pair-permute (within-8 e-columns) --------------
// out[8g + 2j] = in[8g + j], out[8g + 2j + 1] = in[8g + j + 4]   (verified R10)
__global__ void round_perm(const float* __restrict__ src,
                           float* __restrict__ dst, int n4) {
    int i = blockIdx.x * 256 + threadIdx.x;
    if (i >= n4) return;
    int base = 8 * (i >> 1) + 2 * (i & 1);
    float2 a = *(const float2*)(src + base);
    float2 b = *(const float2*)(src + base + 4);
    float4 o = make_float4(rtf(a.x), rtf(b.x), rtf(a.y), rtf(b.y));
    *(float4*)(dst + 4 * i) = o;
}

// plain pre-round (for V path: natural layout)
__global__ void round_only(const float* __restrict__ src,
                           float* __restrict__ dst, int n4) {
    int i = blockIdx.x * 256 + threadIdx.x;
    if (i >= n4) return;
    float4 v = *(const float4*)(src + 4 * i);
    *(float4*)(dst + 4 * i) = make_float4(rtf(v.x), rtf(v.y), rtf(v.z), rtf(v.w));
}

// ---------------- K/V projection GEMM (tf32 mma, cp.async 2-stage) -----------
// Split kernels via z (0=K, 1=V); tile 128m x 64c; paired LDS.64 fragments.
// PJ_STR = 40 (== 8 mod 32): paired loads conflict-free per half-warp phase.
#define PJ_STR 40
#define PJ_WOF (128 * PJ_STR)
#define PJ_BUF (192 * PJ_STR)                 // floats per stage: 7680
#define PJ_SMEM (2 * PJ_BUF * 4)              // 61440 B

__device__ __forceinline__ void pj_issue(uint32_t sb, int stage, int k0,
                                         const float* __restrict__ x,
                                         const float* __restrict__ W,
                                         int m0, int c0, int tid) {
    uint32_t base = sb + stage * (PJ_BUF * 4);
#pragma unroll
    for (int it = 0; it < 4; it++) {           // xs: 128x32 = 1024 chunks
        int i = it * 256 + tid;
        int r = i >> 3, c4 = (i & 7) * 4;
        CP16(base + (r * PJ_STR + c4) * 4,
             x + (size_t)(m0 + r) * E_ + k0 + c4);
    }
#pragma unroll
    for (int it = 0; it < 2; it++) {           // ws: 64x32 = 512 chunks
        int i = it * 256 + tid;
        int r = i >> 3, c4 = (i & 7) * 4;
        CP16(base + (PJ_WOF + r * PJ_STR + c4) * 4,
             W + (size_t)(c0 + r) * E_ + k0 + c4);
    }
    CP_COMMIT();
}

__global__ void __launch_bounds__(256) proj_mma(const float* __restrict__ bk,
                                                const float* __restrict__ bv) {
    extern __shared__ uint32_t smu[];
    uint32_t sb = smem_u32(smu);
    int tid = threadIdx.x;
    int w = tid >> 5, lane = tid & 31;
    int qq = lane & 3, g = lane >> 2;
    int m0 = blockIdx.x * 128;
    int h  = blockIdx.y;
    int c0 = h * 64;
    int z  = blockIdx.z;
    const float* x    = g_xrp;
    const float* W    = z ? g_Wvp : g_Wkp;
    const float* bias = z ? bv : bk;

    float acc[8][4];
#pragma unroll
    for (int i = 0; i < 8; i++)
#pragma unroll
        for (int j = 0; j < 4; j++) acc[i][j] = 0.f;

    pj_issue(sb, 0, 0, x, W, m0, c0, tid);

    for (int ec = 0; ec < 16; ec++) {
        if (ec < 15) pj_issue(sb, (ec + 1) & 1, (ec + 1) * 32, x, W, m0, c0, tid);
        if (ec < 15) { CP_WAIT(1); } else { CP_WAIT(0); }
        __syncthreads();

        const uint32_t* bf = smu + (ec & 1) * PJ_BUF;
        uint32_t af[4][4];
#pragma unroll
        for (int kk = 0; kk < 4; kk++) {
            uint2 lo = *(const uint2*)&bf[(16 * w + g) * PJ_STR + 8 * kk + 2 * qq];
            uint2 hi = *(const uint2*)&bf[(16 * w + g + 8) * PJ_STR + 8 * kk + 2 * qq];
            af[kk][0] = lo.x; af[kk][1] = hi.x; af[kk][2] = lo.y; af[kk][3] = hi.y;
        }
#pragma unroll
        for (int nt = 0; nt < 8; nt++) {
#pragma unroll
            for (int kk = 0; kk < 4; kk++) {
                uint2 bb = *(const uint2*)&bf[PJ_WOF + (8 * nt + g) * PJ_STR + 8 * kk + 2 * qq];
                mma_tf32(acc[nt], af[kk], bb.x, bb.y);
            }
        }
        __syncthreads();
    }

    // epilogue
    int r0 = m0 + 16 * w + g;
    int b0i = r0 >> 11, n0i = r0 & 2047;
    int bh = b0i * 8 + h;
    if (z == 0) {
        // K -> g_Kp [bh][n][d-permuted] (verified R10 mapping)
        float* Kp0 = g_Kp + ((size_t)bh * N_ + n0i) * D_;
#pragma unroll
        for (int nt = 0; nt < 8; nt++) {
            int c = 8 * nt + 2 * qq;
            float bb0 = bias[c0 + c], bb1 = bias[c0 + c + 1];
            int p1 = 8 * nt + (qq < 2 ? 4 * qq : 4 * qq - 7);
            Kp0[p1]              = rtf(acc[nt][0] + bb0);
            Kp0[p1 + 2]          = rtf(acc[nt][1] + bb1);
            Kp0[8 * D_ + p1]     = rtf(acc[nt][2] + bb0);
            Kp0[8 * D_ + p1 + 2] = rtf(acc[nt][3] + bb1);
        }
    } else {
        // V natural [bh][n][d], coalesced float2 stores
        float* p0 = g_V + ((size_t)bh * N_ + n0i) * D_;
        float* p8 = p0 + 8 * D_;
#pragma unroll
        for (int nt = 0; nt < 8; nt++) {
            int c = 8 * nt + 2 * qq;
            float bb0 = bias[c0 + c], bb1 = bias[c0 + c + 1];
            *(float2*)&p0[c] = make_float2(rtf(acc[nt][0] + bb0), rtf(acc[nt][1] + bb1));
            *(float2*)&p8[c] = make_float2(rtf(acc[nt][2] + bb0), rtf(acc[nt][3] + bb1));
        }
    }
}

// ---------------- row-norm kernel (perm-invariant row sums) ------------------
__global__ void __launch_bounds__(256) norm_kernel() {
    __shared__ float red[256];
    int bh = blockIdx.x, tid = threadIdx.x;
    const float* Kb = g_Kp + (size_t)bh * N_ * D_;
    float gm = 0.f;
    for (int r = tid; r < N_; r += 256) {
        const float4* p = (const float4*)(Kb + (size_t)r * D_);
        float s = 0.f;
#pragma unroll
        for (int j = 0; j < 16; j++) {
            float4 v = p[j];
            s += v.x * v.x + v.y * v.y + v.z * v.z + v.w * v.w;
        }
        g_norm2[bh * N_ + r] = s;
        gm = fmaxf(gm, s);
    }
    red[tid] = gm;
    __syncthreads();
    for (int o = 128; o; o >>= 1) {
        if (tid < o) red[tid] = fmaxf(red[tid], red[tid + o]);
        __syncthreads();
    }
    if (tid == 0) g_gmax2[bh] = red[0];
}

// ---------------- tf32 mma flash attention -----------------------------------
// R9 structure. 3-buffer cp.async ring -> ONE barrier/iter (safe at ring>=3).
// S-side paired LDS.64 (K d-permuted, KS_STR==8 mod 32); PV scalar from natural V.
#define KS_STR 72
#define VS_STR 72
#define AT_VOF (64 * KS_STR)                  // 4608 floats
#define AT_BUF (64 * KS_STR + 64 * VS_STR)    // 9216 floats per stage
#define ATTN_SMEM (3 * AT_BUF * 4)            // 110592 B

__device__ __forceinline__ void at_issue(uint32_t sb, int stage, int k0,
                                         const float* __restrict__ Kpb,
                                         const float* __restrict__ Vb, int tid) {
    uint32_t base = sb + stage * (AT_BUF * 4);
#pragma unroll
    for (int it = 0; it < 4; it++) {          // K tile: 64 keys x 64 d
        int i = it * 256 + tid;
        int r = i >> 4, c4 = (i & 15) * 4;
        CP16(base + (r * KS_STR + c4) * 4,
             Kpb + (size_t)(k0 + r) * D_ + c4);
    }
#pragma unroll
    for (int it = 0; it < 4; it++) {          // V tile: 64 keys x 64 d
        int i = it * 256 + tid;
        int r = i >> 4, c4 = (i & 15) * 4;
        CP16(base + (AT_VOF + r * VS_STR + c4) * 4,
             Vb + (size_t)(k0 + r) * D_ + c4);
    }
    CP_COMMIT();
}

__global__ void __launch_bounds__(256, 2) attn_mma(float* __restrict__ out) {
    extern __shared__ uint32_t smu[];
    uint32_t sb = smem_u32(smu);

    int tid = threadIdx.x;
    int w = tid >> 5, lane = tid & 31;
    int qq = lane & 3, g = lane >> 2;
    int quad = lane & 0x1C;
    int src1 = quad | (qq >> 1);
    int src2 = quad | ((qq >> 1) + 2);
    int q0 = blockIdx.x * 128;
    int bh = blockIdx.y;
    int b = bh >> 3, h = bh & 7;

    const float* Kpb = g_Kp + (size_t)bh * N_ * D_;
    const float* Vb  = g_V  + (size_t)bh * N_ * D_;

    // Q fragments: paired float2 gmem loads from d-permuted K (verified R10)
    int qrow = q0 + 16 * w + g;
    uint32_t qf[8][4];
#pragma unroll
    for (int kk = 0; kk < 8; kk++) {
        float2 lo = *(const float2*)&Kpb[(size_t)qrow * D_ + 8 * kk + 2 * qq];
        float2 hi = *(const float2*)&Kpb[(size_t)(qrow + 8) * D_ + 8 * kk + 2 * qq];
        qf[kk][0] = __float_as_uint(lo.x);
        qf[kk][1] = __float_as_uint(hi.x);
        qf[kk][2] = __float_as_uint(lo.y);
        qf[kk][3] = __float_as_uint(hi.y);
    }

    float gmax = g_gmax2[bh];
    float mhat0 = sqrtf(g_norm2[bh * N_ + qrow] * gmax);
    float mhat8 = sqrtf(g_norm2[bh * N_ + qrow + 8] * gmax);

    float oAcc[8][4];
#pragma unroll
    for (int i = 0; i < 8; i++)
#pragma unroll
        for (int j = 0; j < 4; j++) oAcc[i][j] = 0.f;
    float l0 = 0.f, l8 = 0.f;

    at_issue(sb, 0, 0, Kpb, Vb, tid);

    int bi = 0, bnext = 1;
    for (int t = 0; t < 32; t++) {
        if (t < 31) at_issue(sb, bnext, (t + 1) * 64, Kpb, Vb, tid);
        if (t < 31) { CP_WAIT(1); } else { CP_WAIT(0); }
        __syncthreads();

        const uint32_t* Ksb = smu + bi * AT_BUF;
        const uint32_t* Vsb = Ksb + AT_VOF;
        bi = bnext; bnext = (bnext == 2) ? 0 : bnext + 1;

#pragma unroll
        for (int nt = 0; nt < 8; nt++) {
            // ---- S(:, 8nt..8nt+7) = Q K^T (paired B, two 4-deep chains) ----
            float sA[4] = {0.f, 0.f, 0.f, 0.f};
            float sB[4] = {0.f, 0.f, 0.f, 0.f};
            int row = (8 * nt + g) * KS_STR;
#pragma unroll
            for (int kk = 0; kk < 4; kk++) {
                uint2 p0 = *(const uint2*)&Ksb[row + 8 * kk + 2 * qq];
                mma_tf32(sA, qf[kk], p0.x, p0.y);
                uint2 p1 = *(const uint2*)&Ksb[row + 8 * (kk + 4) + 2 * qq];
                mma_tf32(sB, qf[kk + 4], p1.x, p1.y);
            }
            // ---- p = exp(s - mhat); accumulate l ----
            float p0 = __expf(sA[0] + sB[0] - mhat0);
            float p1 = __expf(sA[1] + sB[1] - mhat0);
            float p2 = __expf(sA[2] + sB[2] - mhat8);
            float p3 = __expf(sA[3] + sB[3] - mhat8);
            l0 += p0 + p1;
            l8 += p2 + p3;
            uint32_t c0v = f2tf(p0), c1v = f2tf(p1), c2v = f2tf(p2), c3v = f2tf(p3);
            // ---- C-frag -> A-frag relayout (intra-quad shuffles) ----
            uint32_t t0, t1, a[4];
            t0 = __shfl_sync(0xffffffffu, c0v, src1);
            t1 = __shfl_sync(0xffffffffu, c1v, src1);
            a[0] = (qq & 1) ? t1 : t0;
            t0 = __shfl_sync(0xffffffffu, c2v, src1);
            t1 = __shfl_sync(0xffffffffu, c3v, src1);
            a[1] = (qq & 1) ? t1 : t0;
            t0 = __shfl_sync(0xffffffffu, c0v, src2);
            t1 = __shfl_sync(0xffffffffu, c1v, src2);
            a[2] = (qq & 1) ? t1 : t0;
            t0 = __shfl_sync(0xffffffffu, c2v, src2);
            t1 = __shfl_sync(0xffffffffu, c3v, src2);
            a[3] = (qq & 1) ? t1 : t0;
            // ---- O += P V (scalar B loads, conflict-free) ----
#pragma unroll
            for (int vt = 0; vt < 8; vt++) {
                uint32_t b0 = Vsb[(8 * nt + qq) * VS_STR + 8 * vt + g];
                uint32_t b1 = Vsb[(8 * nt + qq + 4) * VS_STR + 8 * vt + g];
                mma_tf32(oAcc[vt], a, b0, b1);
            }
        }
    }

    // reduce l across the quad
    l0 += __shfl_xor_sync(0xffffffffu, l0, 1);
    l0 += __shfl_xor_sync(0xffffffffu, l0, 2);
    l8 += __shfl_xor_sync(0xffffffffu, l8, 1);
    l8 += __shfl_xor_sync(0xffffffffu, l8, 2);

    const float inv = 0.04419417382415922f;   // 1/sqrt(512)
    float sc0 = inv / l0, sc8 = inv / l8;

    float* op0 = out + ((size_t)b * N_ + qrow) * E_ + h * 64;
    float* op8 = out + ((size_t)b * N_ + qrow + 8) * E_ + h * 64;
#pragma unroll
    for (int vt = 0; vt < 8; vt++) {
        *(float2*)&op0[8 * vt + 2 * qq] = make_float2(oAcc[vt][0] * sc0, oAcc[vt][1] * sc0);
        *(float2*)&op8[8 * vt + 2 * qq] = make_float2(oAcc[vt][2] * sc8, oAcc[vt][3] * sc8);
    }
}

// ---------------- launch ------------------------------------------------------
extern "C" void kernel_launch(void* const* d_in, const int* in_sizes, int n_in,
                              void* d_out, int out_size) {
    const float* x  = (const float*)d_in[0];
    const float* Wk = (const float*)d_in[1];
    const float* bk = (const float*)d_in[2];
    const float* Wv = (const float*)d_in[3];
    const float* bv = (const float*)d_in[4];
    float* out = (float*)d_out;

    float *xp, *Wkp, *Wvp;
    cudaGetSymbolAddress((void**)&xp,  g_xrp);
    cudaGetSymbolAddress((void**)&Wkp, g_Wkp);
    cudaGetSymbolAddress((void**)&Wvp, g_Wvp);

    cudaFuncSetAttribute(proj_mma, cudaFuncAttributeMaxDynamicSharedMemorySize, PJ_SMEM);
    cudaFuncSetAttribute(attn_mma, cudaFuncAttributeMaxDynamicSharedMemorySize, ATTN_SMEM);

    // pre-round + pair-permute inputs (A and B e-columns permuted identically)
    round_perm<<<(B_ * N_ * E_ / 4 + 255) / 256, 256>>>(x, xp, B_ * N_ * E_ / 4);
    round_perm<<<(E_ * E_ / 4 + 255) / 256, 256>>>(Wk, Wkp, E_ * E_ / 4);
    round_perm<<<(E_ * E_ / 4 + 255) / 256, 256>>>(Wv, Wvp, E_ * E_ / 4);

    // K and V projections (split kernels: z = 0 -> K, z = 1 -> V)
    proj_mma<<<dim3(64, 8, 2), 256, PJ_SMEM>>>(bk, bv);

    norm_kernel<<<BH_, 256>>>();

    attn_mma<<<dim3(N_ / 128, BH_), 256, ATTN_SMEM>>>(out);
}

// round 13
// speedup vs baseline: 2.4310x; 1.7856x over previous
#include <cuda_runtime.h>
#include <cuda_fp16.h>
#include <math.h>
#include <cstdint>

// Problem constants
#define B_  4
#define N_  2048
#define E_  512
#define H_  8
#define D_  64
#define BH_ 32   // B_*H_

// ---------------- scratch (static __device__; no allocations allowed) -------
__device__ __half g_xh [B_ * N_ * E_];    // x, fp16
__device__ __half g_Wkh[E_ * E_];         // Wk, fp16
__device__ __half g_Wvh[E_ * E_];         // Wv, fp16
__device__ __half g_Kh [BH_ * N_ * D_];   // K [bh][n][d] natural fp16
__device__ __half g_Vh [BH_ * N_ * D_];   // V [bh][n][d] natural fp16
__device__ __half g_VTh[BH_ * D_ * N_];   // V^T [bh][d][n] fp16

// ---------------- helpers (sm_80-era PTX only) --------------------------------
__device__ __forceinline__ void mma_f16(float* d, const uint32_t* a,
                                        uint32_t b0, uint32_t b1) {
    asm volatile(
        "mma.sync.aligned.m16n8k16.row.col.f32.f16.f16.f32 "
        "{%0,%1,%2,%3}, {%4,%5,%6,%7}, {%8,%9}, {%0,%1,%2,%3};\n"
        : "+f"(d[0]), "+f"(d[1]), "+f"(d[2]), "+f"(d[3])
        : "r"(a[0]), "r"(a[1]), "r"(a[2]), "r"(a[3]), "r"(b0), "r"(b1));
}
__device__ __forceinline__ uint32_t pack2(float x, float y) {
    __half2 h = __floats2half2_rn(x, y);
    return *(uint32_t*)&h;
}
__device__ __forceinline__ uint32_t smem_u32(const void* p) {
    uint32_t a;
    asm("{ .reg .u64 t; cvta.to.shared.u64 t, %1; cvt.u32.u64 %0, t; }"
        : "=r"(a) : "l"(p));
    return a;
}
#define CP16(dst, src) \
    asm volatile("cp.async.cg.shared.global [%0], [%1], 16;" :: "r"(dst), "l"(src) : "memory")
#define CP_COMMIT() asm volatile("cp.async.commit_group;" ::: "memory")
#define CP_WAIT(n)  asm volatile("cp.async.wait_group %0;" :: "n"(n) : "memory")

// ---------------- fp32 -> fp16 conversion kernel ------------------------------
__global__ void round_h(const float* __restrict__ src,
                        __half* __restrict__ dst, int n4) {
    int i = blockIdx.x * 256 + threadIdx.x;
    if (i >= n4) return;
    float4 v = *(const float4*)(src + 4 * i);
    uint2 o = make_uint2(pack2(v.x, v.y), pack2(v.z, v.w));
    *(uint2*)(dst + 4 * i) = o;
}

// ---------------- K/V projection GEMM (fp16 mma, cp.async 2-stage) -----------
// Tile 128m x 64c (one head per y), z: 0=K, 1=V. 16 e-chunks of 32 (2 ksteps).
// Row stride 40 halfs (80 B): all fragment LDS conflict-free.
#define PJ_STRH 40
#define PJ_WOFH (128 * PJ_STRH)              // 5120 halfs
#define PJ_BUFH (192 * PJ_STRH)              // 7680 halfs per stage
#define PJ_SMEM (2 * PJ_BUFH * 2)            // 30720 B

__device__ __forceinline__ void pj_issue(uint32_t sb, int stage, int k0,
                                         const __half* __restrict__ x,
                                         const __half* __restrict__ W,
                                         int m0, int c0, int tid) {
    uint32_t base = sb + stage * (PJ_BUFH * 2);
#pragma unroll
    for (int it = 0; it < 2; it++) {           // xs: 128 rows x 4 chunks = 512
        int i = it * 256 + tid;
        int r = i >> 2, c8 = (i & 3) * 8;
        CP16(base + (r * PJ_STRH + c8) * 2,
             x + (size_t)(m0 + r) * E_ + k0 + c8);
    }
    {                                          // ws: 64 rows x 4 chunks = 256
        int i = tid;
        int r = i >> 2, c8 = (i & 3) * 8;
        CP16(base + (PJ_WOFH + r * PJ_STRH + c8) * 2,
             W + (size_t)(c0 + r) * E_ + k0 + c8);
    }
    CP_COMMIT();
}

__global__ void __launch_bounds__(256) proj_mma(const float* __restrict__ bk,
                                                const float* __restrict__ bv) {
    extern __shared__ __half smh[];
    uint32_t sb = smem_u32(smh);
    int tid = threadIdx.x;
    int w = tid >> 5, lane = tid & 31;
    int qq = lane & 3, g = lane >> 2;
    int m0 = blockIdx.x * 128;
    int h  = blockIdx.y;
    int c0 = h * 64;
    int z  = blockIdx.z;
    const __half* x    = g_xh;
    const __half* W    = z ? g_Wvh : g_Wkh;
    const float*  bias = z ? bv : bk;
    __half* dst        = z ? g_Vh : g_Kh;

    float acc[8][4];
#pragma unroll
    for (int i = 0; i < 8; i++)
#pragma unroll
        for (int j = 0; j < 4; j++) acc[i][j] = 0.f;

    pj_issue(sb, 0, 0, x, W, m0, c0, tid);

    for (int ec = 0; ec < 16; ec++) {
        if (ec < 15) pj_issue(sb, (ec + 1) & 1, (ec + 1) * 32, x, W, m0, c0, tid);
        if (ec < 15) { CP_WAIT(1); } else { CP_WAIT(0); }
        __syncthreads();

        const __half* bf = smh + (ec & 1) * PJ_BUFH;
        uint32_t af[2][4];
#pragma unroll
        for (int kk = 0; kk < 2; kk++) {
            af[kk][0] = *(const uint32_t*)&bf[(16 * w + g) * PJ_STRH + 16 * kk + 2 * qq];
            af[kk][1] = *(const uint32_t*)&bf[(16 * w + g + 8) * PJ_STRH + 16 * kk + 2 * qq];
            af[kk][2] = *(const uint32_t*)&bf[(16 * w + g) * PJ_STRH + 16 * kk + 8 + 2 * qq];
            af[kk][3] = *(const uint32_t*)&bf[(16 * w + g + 8) * PJ_STRH + 16 * kk + 8 + 2 * qq];
        }
#pragma unroll
        for (int nt = 0; nt < 8; nt++) {
#pragma unroll
            for (int kk = 0; kk < 2; kk++) {
                uint32_t b0 = *(const uint32_t*)&bf[PJ_WOFH + (8 * nt + g) * PJ_STRH + 16 * kk + 2 * qq];
                uint32_t b1 = *(const uint32_t*)&bf[PJ_WOFH + (8 * nt + g) * PJ_STRH + 16 * kk + 8 + 2 * qq];
                mma_f16(acc[nt], af[kk], b0, b1);
            }
        }
        __syncthreads();
    }

    // epilogue: bias add in fp32, pack to fp16, natural layout (half2 stores)
    int r0 = m0 + 16 * w + g;
    int b0i = r0 >> 11, n0i = r0 & 2047;
    int bh = b0i * 8 + h;
    __half* p0 = dst + ((size_t)bh * N_ + n0i) * D_;
    __half* p8 = p0 + 8 * D_;
#pragma unroll
    for (int nt = 0; nt < 8; nt++) {
        int c = 8 * nt + 2 * qq;
        float bb0 = bias[c0 + c], bb1 = bias[c0 + c + 1];
        *(uint32_t*)&p0[c] = pack2(acc[nt][0] + bb0, acc[nt][1] + bb1);
        *(uint32_t*)&p8[c] = pack2(acc[nt][2] + bb0, acc[nt][3] + bb1);
    }
}

// ---------------- V transpose (fp16): [bh][n][d] -> [bh][d][n] ---------------
__global__ void __launch_bounds__(256) vtrans() {
    __shared__ __half t[64][65];
    int bh = blockIdx.y;
    int n0 = blockIdx.x * 64;
    int tid = threadIdx.x;
    const __half* src = g_Vh + ((size_t)bh * N_ + n0) * D_;
#pragma unroll
    for (int it = 0; it < 16; it++) {
        int i = it * 256 + tid;
        int r = i >> 6, c = i & 63;
        t[r][c] = src[(size_t)r * D_ + c];
    }
    __syncthreads();
    __half* dstb = g_VTh + (size_t)bh * D_ * N_ + n0;
#pragma unroll
    for (int it = 0; it < 16; it++) {
        int i = it * 256 + tid;
        int d = i >> 6, n = i & 63;
        dstb[(size_t)d * N_ + n] = t[n][d];
    }
}

// ---------------- fp16 mma flash attention (online max) ----------------------
// 3-buffer cp.async ring, ONE barrier/iter. Online (exact) row max -> p <= 1,
// no fp16 overflow/underflow of significant terms. C-frag -> A-frag by direct
// half2 pack (no shuffles). Per-tile: S (32 regs) -> quad-max -> rescale -> PV.
#define KS_STRH 72
#define AT_VOFH (64 * KS_STRH)                // 4608 halfs
#define AT_BUFH (2 * 64 * KS_STRH)            // 9216 halfs per stage
#define ATTN_SMEM (3 * AT_BUFH * 2)           // 55296 B

__device__ __forceinline__ void at_issue(uint32_t sb, int stage, int k0,
                                         const __half* __restrict__ Kb,
                                         const __half* __restrict__ VTb, int tid) {
    uint32_t base = sb + stage * (AT_BUFH * 2);
#pragma unroll
    for (int it = 0; it < 2; it++) {          // K tile: 64 keys x 8 chunks = 512
        int i = it * 256 + tid;
        int r = i >> 3, c8 = (i & 7) * 8;
        CP16(base + (r * KS_STRH + c8) * 2,
             Kb + (size_t)(k0 + r) * D_ + c8);
    }
#pragma unroll
    for (int it = 0; it < 2; it++) {          // V^T tile: 64 d x 8 chunks = 512
        int i = it * 256 + tid;
        int r = i >> 3, c8 = (i & 7) * 8;
        CP16(base + (AT_VOFH + r * KS_STRH + c8) * 2,
             VTb + (size_t)r * N_ + k0 + c8);
    }
    CP_COMMIT();
}

__global__ void __launch_bounds__(256, 2) attn_mma(float* __restrict__ out) {
    extern __shared__ __half smh[];
    uint32_t sb = smem_u32(smh);

    int tid = threadIdx.x;
    int w = tid >> 5, lane = tid & 31;
    int qq = lane & 3, g = lane >> 2;
    int q0 = blockIdx.x * 128;
    int bh = blockIdx.y;
    int b = bh >> 3, h = bh & 7;

    const __half* Kb  = g_Kh  + (size_t)bh * N_ * D_;
    const __half* VTb = g_VTh + (size_t)bh * D_ * N_;

    // Q fragments: contiguous half2 gmem loads (natural layout)
    int qrow = q0 + 16 * w + g;
    uint32_t qf[4][4];
#pragma unroll
    for (int dk = 0; dk < 4; dk++) {
        qf[dk][0] = *(const uint32_t*)&Kb[(size_t)qrow * D_ + 16 * dk + 2 * qq];
        qf[dk][1] = *(const uint32_t*)&Kb[(size_t)(qrow + 8) * D_ + 16 * dk + 2 * qq];
        qf[dk][2] = *(const uint32_t*)&Kb[(size_t)qrow * D_ + 16 * dk + 8 + 2 * qq];
        qf[dk][3] = *(const uint32_t*)&Kb[(size_t)(qrow + 8) * D_ + 16 * dk + 8 + 2 * qq];
    }

    float oAcc[8][4];
#pragma unroll
    for (int i = 0; i < 8; i++)
#pragma unroll
        for (int j = 0; j < 4; j++) oAcc[i][j] = 0.f;
    float m0 = -1e30f, m8 = -1e30f, l0 = 0.f, l8 = 0.f;

    at_issue(sb, 0, 0, Kb, VTb, tid);

    int bi = 0, bnext = 1;
    for (int t = 0; t < 32; t++) {
        if (t < 31) at_issue(sb, bnext, (t + 1) * 64, Kb, VTb, tid);
        if (t < 31) { CP_WAIT(1); } else { CP_WAIT(0); }
        __syncthreads();

        const __half* Ksb = smh + bi * AT_BUFH;
        const __half* Vsb = Ksb + AT_VOFH;
        bi = bnext; bnext = (bnext == 2) ? 0 : bnext + 1;

        // ---- S for all 64 keys of this tile (kept in registers) ----
        // s[kk][0..3] = keys 16kk+2qq,+1 rows (g, g, g+8, g+8)   [E subtile]
        // s[kk][4..7] = keys 16kk+8+2qq,+1 same rows             [O subtile]
        float s[4][8];
#pragma unroll
        for (int kk = 0; kk < 4; kk++) {
#pragma unroll
            for (int j = 0; j < 8; j++) s[kk][j] = 0.f;
            int rowE = (16 * kk + g) * KS_STRH;
            int rowO = (16 * kk + 8 + g) * KS_STRH;
#pragma unroll
            for (int dk = 0; dk < 4; dk++) {
                uint32_t e0 = *(const uint32_t*)&Ksb[rowE + 16 * dk + 2 * qq];
                uint32_t e1 = *(const uint32_t*)&Ksb[rowE + 16 * dk + 8 + 2 * qq];
                mma_f16(&s[kk][0], qf[dk], e0, e1);
                uint32_t o0 = *(const uint32_t*)&Ksb[rowO + 16 * dk + 2 * qq];
                uint32_t o1 = *(const uint32_t*)&Ksb[rowO + 16 * dk + 8 + 2 * qq];
                mma_f16(&s[kk][4], qf[dk], o0, o1);
            }
        }

        // ---- online max (exact, per row) ----
        float r0 = s[0][0], r8 = s[0][2];
#pragma unroll
        for (int kk = 0; kk < 4; kk++) {
            r0 = fmaxf(r0, fmaxf(fmaxf(s[kk][0], s[kk][1]), fmaxf(s[kk][4], s[kk][5])));
            r8 = fmaxf(r8, fmaxf(fmaxf(s[kk][2], s[kk][3]), fmaxf(s[kk][6], s[kk][7])));
        }
        r0 = fmaxf(r0, __shfl_xor_sync(0xffffffffu, r0, 1));
        r0 = fmaxf(r0, __shfl_xor_sync(0xffffffffu, r0, 2));
        r8 = fmaxf(r8, __shfl_xor_sync(0xffffffffu, r8, 1));
        r8 = fmaxf(r8, __shfl_xor_sync(0xffffffffu, r8, 2));
        float m0n = fmaxf(m0, r0), m8n = fmaxf(m8, r8);
        float al0 = __expf(m0 - m0n), al8 = __expf(m8 - m8n);
        m0 = m0n; m8 = m8n;
        l0 *= al0; l8 *= al8;
#pragma unroll
        for (int vt = 0; vt < 8; vt++) {
            oAcc[vt][0] *= al0; oAcc[vt][1] *= al0;
            oAcc[vt][2] *= al8; oAcc[vt][3] *= al8;
        }

        // ---- exp, accumulate l, pack P, PV ----
#pragma unroll
        for (int kk = 0; kk < 4; kk++) {
            float pE0 = __expf(s[kk][0] - m0), pE1 = __expf(s[kk][1] - m0);
            float pE2 = __expf(s[kk][2] - m8), pE3 = __expf(s[kk][3] - m8);
            float pO0 = __expf(s[kk][4] - m0), pO1 = __expf(s[kk][5] - m0);
            float pO2 = __expf(s[kk][6] - m8), pO3 = __expf(s[kk][7] - m8);
            l0 += pE0 + pE1 + pO0 + pO1;
            l8 += pE2 + pE3 + pO2 + pO3;
            uint32_t a[4];
            a[0] = pack2(pE0, pE1);   // row g,   k-local 2qq,+1
            a[1] = pack2(pE2, pE3);   // row g+8
            a[2] = pack2(pO0, pO1);   // row g,   k-local 8+2qq,+1
            a[3] = pack2(pO2, pO3);   // row g+8
#pragma unroll
            for (int vt = 0; vt < 8; vt++) {
                int vrow = (8 * vt + g) * KS_STRH;
                uint32_t b0 = *(const uint32_t*)&Vsb[vrow + 16 * kk + 2 * qq];
                uint32_t b1 = *(const uint32_t*)&Vsb[vrow + 16 * kk + 8 + 2 * qq];
                mma_f16(oAcc[vt], a, b0, b1);
            }
        }
    }

    // reduce l across the quad (lanes share rows)
    l0 += __shfl_xor_sync(0xffffffffu, l0, 1);
    l0 += __shfl_xor_sync(0xffffffffu, l0, 2);
    l8 += __shfl_xor_sync(0xffffffffu, l8, 1);
    l8 += __shfl_xor_sync(0xffffffffu, l8, 2);

    const float inv = 0.04419417382415922f;   // 1/sqrt(512)
    float sc0 = inv / l0, sc8 = inv / l8;

    float* op0 = out + ((size_t)b * N_ + qrow) * E_ + h * 64;
    float* op8 = out + ((size_t)b * N_ + qrow + 8) * E_ + h * 64;
#pragma unroll
    for (int vt = 0; vt < 8; vt++) {
        *(float2*)&op0[8 * vt + 2 * qq] = make_float2(oAcc[vt][0] * sc0, oAcc[vt][1] * sc0);
        *(float2*)&op8[8 * vt + 2 * qq] = make_float2(oAcc[vt][2] * sc8, oAcc[vt][3] * sc8);
    }
}

// ---------------- launch ------------------------------------------------------
extern "C" void kernel_launch(void* const* d_in, const int* in_sizes, int n_in,
                              void* d_out, int out_size) {
    const float* x  = (const float*)d_in[0];
    const float* Wk = (const float*)d_in[1];
    const float* bk = (const float*)d_in[2];
    const float* Wv = (const float*)d_in[3];
    const float* bv = (const float*)d_in[4];
    float* out = (float*)d_out;

    __half *xh, *Wkh, *Wvh;
    cudaGetSymbolAddress((void**)&xh,  g_xh);
    cudaGetSymbolAddress((void**)&Wkh, g_Wkh);
    cudaGetSymbolAddress((void**)&Wvh, g_Wvh);

    cudaFuncSetAttribute(proj_mma, cudaFuncAttributeMaxDynamicSharedMemorySize, PJ_SMEM);
    cudaFuncSetAttribute(attn_mma, cudaFuncAttributeMaxDynamicSharedMemorySize, ATTN_SMEM);

    // fp32 -> fp16 input conversion
    round_h<<<(B_ * N_ * E_ / 4 + 255) / 256, 256>>>(x, xh, B_ * N_ * E_ / 4);
    round_h<<<(E_ * E_ / 4 + 255) / 256, 256>>>(Wk, Wkh, E_ * E_ / 4);
    round_h<<<(E_ * E_ / 4 + 255) / 256, 256>>>(Wv, Wvh, E_ * E_ / 4);

    // K and V projections (z = 0 -> K, z = 1 -> V), natural fp16 outputs
    proj_mma<<<dim3(64, 8, 2), 256, PJ_SMEM>>>(bk, bv);

    // V transpose for PV B-fragments
    vtrans<<<dim3(32, BH_), 256>>>();

    attn_mma<<<dim3(N_ / 128, BH_), 256, ATTN_SMEM>>>(out);
}